// round 8
// baseline (speedup 1.0000x reference)
#include <cuda_runtime.h>
#include <cuda_bf16.h>
#include <math.h>
#include <stdint.h>

// Problem constants
#define BN 16
#define DDIM 256
#define TT 2048
#define KK 1024
#define NPTS (BN*TT)        // 32768 points
#define NQ (BN*DDIM*TT)     // 8388608 elements
#define DELTA_TC 1e-5f      // bf16 3-term split score error ~1e-7; 100x margin

// ---------------- Device scratch ----------------
__device__ __nv_bfloat16 g_xhi[(size_t)NPTS * DDIM];
__device__ __nv_bfloat16 g_xlo[(size_t)NPTS * DDIM];
__device__ __nv_bfloat16 g_ehi[KK * DDIM];
__device__ __nv_bfloat16 g_elo[KK * DDIM];
__device__ float  g_c2[KK];
__device__ int    g_enc[NPTS];
__device__ int    g_sidx[NPTS];      // second-best index (for flagged points)
__device__ int    g_nflag;
__device__ int    g_flags[NPTS];
__device__ double g_bsum[8192];

// ---------------- baseline-PTX helpers ----------------
__device__ __forceinline__ uint32_t smem_u32(const void* p) {
    uint32_t a;
    asm("{ .reg .u64 t; cvta.to.shared.u64 t, %1; cvt.u32.u64 %0, t; }" : "=r"(a) : "l"(p));
    return a;
}
__device__ __forceinline__ void cpasync16(uint32_t dst, const void* src) {
    asm volatile("cp.async.cg.shared.global [%0], [%1], 16;"
                 :: "r"(dst), "l"(__cvta_generic_to_global(src)) : "memory");
}
#define CP_COMMIT() asm volatile("cp.async.commit_group;" ::: "memory")
#define CP_WAIT0()  asm volatile("cp.async.wait_group 0;" ::: "memory")

__device__ __forceinline__ void ldm_x4(uint32_t a, uint32_t& r0, uint32_t& r1,
                                       uint32_t& r2, uint32_t& r3) {
    asm volatile("ldmatrix.sync.aligned.m8n8.x4.shared.b16 {%0,%1,%2,%3}, [%4];"
                 : "=r"(r0), "=r"(r1), "=r"(r2), "=r"(r3) : "r"(a));
}
__device__ __forceinline__ void mma_bf16(float* d, const uint32_t* a,
                                         uint32_t b0, uint32_t b1) {
    asm volatile("mma.sync.aligned.m16n8k16.row.col.f32.bf16.bf16.f32 "
                 "{%0,%1,%2,%3}, {%4,%5,%6,%7}, {%8,%9}, {%0,%1,%2,%3};"
                 : "+f"(d[0]), "+f"(d[1]), "+f"(d[2]), "+f"(d[3])
                 : "r"(a[0]), "r"(a[1]), "r"(a[2]), "r"(a[3]), "r"(b0), "r"(b1));
}

// top-2 merge: (b1,i1,s1,si1) (self, modified) with (b2,i2,s2,si2)
__device__ __forceinline__ void merge_top2(float& b1, int& i1, float& s1, int& si1,
                                           float b2, int i2, float s2, int si2) {
    if (b2 < b1 || (b2 == b1 && i2 < i1)) {
        float ob = b1; int oi = i1;
        b1 = b2; i1 = i2;
        if (ob < s2 || (ob == s2 && oi < si2)) { s1 = ob; si1 = oi; }
        else { s1 = s2; si1 = si2; }
    } else {
        if (b2 < s1 || (b2 == s1 && i2 < si1)) { s1 = b2; si1 = i2; }
    }
}

// ---------------- prep: bf16 hi/lo splits + ||e||^2 (+ flag init) ----------------
__global__ __launch_bounds__(256) void k_prep_e(const float* __restrict__ emb) {
    __shared__ float red[256];
    int k = blockIdx.x, d = threadIdx.x;
    if (k == 0 && d == 0) g_nflag = 0;
    float v = emb[k * DDIM + d];
    __nv_bfloat16 hi = __float2bfloat16(v);
    float hf = __bfloat162float(hi);
    __nv_bfloat16 lo = __float2bfloat16(v - hf);
    g_ehi[k * DDIM + d] = hi;
    g_elo[k * DDIM + d] = lo;
    red[d] = v * v;
    __syncthreads();
    for (int off = 128; off > 0; off >>= 1) {
        if (d < off) red[d] += red[d + off];
        __syncthreads();
    }
    if (d == 0) g_c2[k] = red[0];
}

__global__ __launch_bounds__(256) void k_prep_x(const float* __restrict__ x) {
    __shared__ float tile[32][33];
    int t0 = blockIdx.x * 32, d0 = blockIdx.y * 32, b = blockIdx.z;
    int tx = threadIdx.x, ty = threadIdx.y;
    #pragma unroll
    for (int j = 0; j < 4; j++) {
        int r = ty + j * 8;
        tile[r][tx] = x[((size_t)(b * DDIM + d0 + r)) * TT + t0 + tx];
    }
    __syncthreads();
    #pragma unroll
    for (int j = 0; j < 4; j++) {
        int r = ty + j * 8;
        size_t n = (size_t)b * TT + t0 + r;
        float v = tile[tx][r];
        __nv_bfloat16 hi = __float2bfloat16(v);
        float hf = __bfloat162float(hi);
        __nv_bfloat16 lo = __float2bfloat16(v - hf);
        g_xhi[n * DDIM + d0 + tx] = hi;
        g_xlo[n * DDIM + d0 + tx] = lo;
    }
}

// ---------------- Pass A: mma.sync bf16 3-term GEMM + fused argmin ----------------
// Tile: M=64 points per CTA (grid 512), 16 N-phases of 64 codes, kc=32 dims.
// smem 45KB -> 4 CTAs/SM (8 warps/SMSP) for tensor-pipe supply.
#define ROWB 80                  // bytes per smem row (32 b16 + 8 pad)
#define MATB (64 * ROWB)         // 5120 B per matrix chunk (64 rows)
#define BUFB (4 * MATB)          // Ahi,Alo,Bhi,Blo = 20480
#define C2OFF (2 * BUFB)         // 40960
#define GEMM_DSMEM (C2OFF + KK * 4)   // 45056

__device__ __forceinline__ void issue_chunk(int q, uint32_t base, int tid, int m0) {
    int ph = q >> 3, kc = q & 7;
    const __nv_bfloat16* xh = g_xhi + (size_t)m0 * DDIM;
    const __nv_bfloat16* xl = g_xlo + (size_t)m0 * DDIM;
    const __nv_bfloat16* eh = g_ehi + (size_t)(ph * 64) * DDIM;
    const __nv_bfloat16* el = g_elo + (size_t)(ph * 64) * DDIM;
    int row = tid >> 2, c16 = tid & 3;          // 64 rows x 4 16B-chunks
    int gof = row * DDIM + kc * 32 + c16 * 8;
    uint32_t so = (uint32_t)(row * ROWB + c16 * 16);
    cpasync16(base + 0 * MATB + so, xh + gof);
    cpasync16(base + 1 * MATB + so, xl + gof);
    cpasync16(base + 2 * MATB + so, eh + gof);
    cpasync16(base + 3 * MATB + so, el + gof);
}

__global__ void __launch_bounds__(256, 4) k_gemm() {
    extern __shared__ char dsm[];
    __shared__ float s_mb[2][64];
    __shared__ float s_ms[2][64];
    __shared__ int   s_mi[2][64];
    __shared__ int   s_msi[2][64];

    const uint32_t smb = smem_u32(dsm);
    float* c2s = (float*)(dsm + C2OFF);

    const int tid = threadIdx.x;
    const int wid = tid >> 5;
    const int lane = tid & 31;
    const int wm = wid >> 1;       // 0..3 (M, 16 rows each)
    const int wn = wid & 1;        // 0..1 (N, 32 codes each)
    const int m0 = blockIdx.x * 64;

    for (int i = tid; i < KK; i += 256) c2s[i] = g_c2[i];

    const int a_row = lane & 15;
    const int a_c8  = (lane >> 4) * 8;
    // B paired-x4: lanes 0-15 -> nt, lanes 16-31 -> nt+1
    const int b_row4  = lane & 7;
    const int b_c84   = ((lane >> 3) & 1) * 8;
    const int b_ntoff = lane >> 4;

    float best[2] = {1e30f, 1e30f};
    float sec[2]  = {1e30f, 1e30f};
    int   bidx[2] = {0, 0};
    int   sidx[2] = {0, 0};

    issue_chunk(0, smb, tid, m0);
    CP_COMMIT();
    int buf = 0;

    for (int ph = 0; ph < 16; ph++) {
        float acc[4][4];
        #pragma unroll
        for (int nt = 0; nt < 4; nt++)
            #pragma unroll
            for (int r = 0; r < 4; r++) acc[nt][r] = 0.f;

        for (int kc = 0; kc < 8; kc++) {
            CP_WAIT0();
            __syncthreads();
            int q = ph * 8 + kc;
            if (q < 127) {
                issue_chunk(q + 1, smb + (uint32_t)((buf ^ 1) * BUFB), tid, m0);
                CP_COMMIT();
            }

            const uint32_t ab  = smb + (uint32_t)(buf * BUFB);
            const uint32_t alb = ab + MATB;
            const uint32_t bb  = ab + 2 * MATB;
            const uint32_t blb = ab + 3 * MATB;

            #pragma unroll
            for (int ks = 0; ks < 2; ks++) {
                const int kb = ks * 16;
                uint32_t ao = (uint32_t)((wm * 16 + a_row) * ROWB + (kb + a_c8) * 2);
                uint32_t ah[4], al[4];
                ldm_x4(ab + ao,  ah[0], ah[1], ah[2], ah[3]);
                ldm_x4(alb + ao, al[0], al[1], al[2], al[3]);

                uint32_t bh[4][2], bl[4][2];
                #pragma unroll
                for (int jj = 0; jj < 2; jj++) {
                    int ntp = jj * 2;
                    uint32_t bo = (uint32_t)((wn * 32 + (ntp + b_ntoff) * 8 + b_row4) * ROWB
                                             + (kb + b_c84) * 2);
                    ldm_x4(bb + bo,  bh[ntp][0], bh[ntp][1], bh[ntp+1][0], bh[ntp+1][1]);
                    ldm_x4(blb + bo, bl[ntp][0], bl[ntp][1], bl[ntp+1][0], bl[ntp+1][1]);
                }
                #pragma unroll
                for (int nt = 0; nt < 4; nt++)
                    mma_bf16(acc[nt], ah, bh[nt][0], bh[nt][1]);
                #pragma unroll
                for (int nt = 0; nt < 4; nt++)
                    mma_bf16(acc[nt], al, bh[nt][0], bh[nt][1]);
                #pragma unroll
                for (int nt = 0; nt < 4; nt++)
                    mma_bf16(acc[nt], ah, bl[nt][0], bl[nt][1]);
            }
            buf ^= 1;
        }

        // epilogue: scores + top-2 (rows: wm*16 + h*8 + lane/4)
        #pragma unroll
        for (int h = 0; h < 2; h++) {
            #pragma unroll
            for (int nt = 0; nt < 4; nt++) {
                int k0 = ph * 64 + wn * 32 + nt * 8 + (lane & 3) * 2;
                float s0 = fmaf(-2.f, acc[nt][2 * h + 0], c2s[k0]);
                float s1 = fmaf(-2.f, acc[nt][2 * h + 1], c2s[k0 + 1]);
                if (s0 < best[h]) {
                    sec[h] = best[h]; sidx[h] = bidx[h];
                    best[h] = s0; bidx[h] = k0;
                } else if (s0 < sec[h]) { sec[h] = s0; sidx[h] = k0; }
                if (s1 < best[h]) {
                    sec[h] = best[h]; sidx[h] = bidx[h];
                    best[h] = s1; bidx[h] = k0 + 1;
                } else if (s1 < sec[h]) { sec[h] = s1; sidx[h] = k0 + 1; }
            }
        }
    }

    // merge: quad shfl (4 lanes share a row), then the 2 N-warps via smem
    #pragma unroll
    for (int h = 0; h < 2; h++) {
        float b = best[h], s = sec[h];
        int i = bidx[h], si = sidx[h];
        #pragma unroll
        for (int off = 1; off <= 2; off <<= 1) {
            float ob  = __shfl_xor_sync(0xffffffffu, b, off);
            float os  = __shfl_xor_sync(0xffffffffu, s, off);
            int   oi  = __shfl_xor_sync(0xffffffffu, i, off);
            int   osi = __shfl_xor_sync(0xffffffffu, si, off);
            merge_top2(b, i, s, si, ob, oi, os, osi);
        }
        if ((lane & 3) == 0) {
            int row = wm * 16 + h * 8 + (lane >> 2);
            s_mb[wn][row] = b; s_ms[wn][row] = s;
            s_mi[wn][row] = i; s_msi[wn][row] = si;
        }
    }
    __syncthreads();
    if (tid < 64) {
        float b = s_mb[0][tid], s = s_ms[0][tid];
        int i = s_mi[0][tid], si = s_msi[0][tid];
        merge_top2(b, i, s, si, s_mb[1][tid], s_mi[1][tid], s_ms[1][tid], s_msi[1][tid]);
        int n = m0 + tid;
        g_enc[n] = i;
        if (s - b < DELTA_TC) {
            g_sidx[n] = si;
            int pos = atomicAdd(&g_nflag, 1);
            g_flags[pos] = n;
        }
    }
}

// ---------------- Pass B: exact fp64 top-2 compare, one warp per point ----------------
__global__ __launch_bounds__(256) void k_passB(const float* __restrict__ x,
                                               const float* __restrict__ emb) {
    const int nf = g_nflag;
    const int gw = (blockIdx.x * blockDim.x + threadIdx.x) >> 5;
    const int nw = (gridDim.x * blockDim.x) >> 5;
    const int lane = threadIdx.x & 31;

    for (int fi = gw; fi < nf; fi += nw) {
        int n = g_flags[fi];
        int i1 = g_enc[n], i2 = g_sidx[n];
        int b = n / TT, t = n % TT;
        const float* xb = x + (size_t)b * DDIM * TT + t;
        double a1 = 0.0, a2 = 0.0;
        #pragma unroll
        for (int j = 0; j < 8; j++) {
            int d = lane * 8 + j;
            double xv = (double)xb[(size_t)d * TT];
            double e1 = (double)emb[i1 * DDIM + d];
            double e2 = (double)emb[i2 * DDIM + d];
            double f1 = xv - e1, f2 = xv - e2;
            a1 = fma(f1, f1, a1);
            a2 = fma(f2, f2, a2);
        }
        #pragma unroll
        for (int off = 16; off > 0; off >>= 1) {
            a1 += __shfl_down_sync(0xffffffffu, a1, off);
            a2 += __shfl_down_sync(0xffffffffu, a2, off);
        }
        if (lane == 0) {
            if (a2 < a1 || (a2 == a1 && i2 < i1)) g_enc[n] = i2;
        }
    }
}

// ---------------- quantized_st + MSE partials ----------------
__global__ __launch_bounds__(256) void k_quant(const float* __restrict__ x,
                                               const float* __restrict__ emb,
                                               float* __restrict__ out,
                                               int do_store) {
    __shared__ float sf[256];
    const int tid = threadIdx.x;
    const int gi = blockIdx.x * 256 + tid;
    const size_t base = (size_t)gi * 4;

    int t = (int)(base % TT);
    size_t tmp = base / TT;
    int d = (int)(tmp % DDIM);
    int b = (int)(tmp / DDIM);

    float4 xv = *(const float4*)&x[base];
    int nb = b * TT + t;
    int i0 = g_enc[nb + 0];
    int i1 = g_enc[nb + 1];
    int i2 = g_enc[nb + 2];
    int i3 = g_enc[nb + 3];
    float q0 = __ldg(&emb[i0 * DDIM + d]);
    float q1 = __ldg(&emb[i1 * DDIM + d]);
    float q2 = __ldg(&emb[i2 * DDIM + d]);
    float q3 = __ldg(&emb[i3 * DDIM + d]);
    float d0 = q0 - xv.x;
    float d1 = q1 - xv.y;
    float d2 = q2 - xv.z;
    float d3 = q3 - xv.w;
    if (do_store) {
        float4 ov = make_float4(xv.x + d0, xv.y + d1, xv.z + d2, xv.w + d3);
        *(float4*)&out[base] = ov;
    }
    float loc = d0 * d0;
    loc = fmaf(d1, d1, loc);
    loc = fmaf(d2, d2, loc);
    loc = fmaf(d3, d3, loc);

    sf[tid] = loc;
    __syncthreads();
    for (int off = 128; off > 0; off >>= 1) {
        if (tid < off) sf[tid] += sf[tid + off];
        __syncthreads();
    }
    if (tid == 0) g_bsum[blockIdx.x] = (double)sf[0];
}

// Block 0: deterministic final MSE reduce + scalars. Blocks 1..128: indices.
__global__ void k_finish(float* __restrict__ out, int out_size) {
    if (blockIdx.x == 0) {
        __shared__ double sd[256];
        const int tid = threadIdx.x;
        double loc = 0.0;
        for (int i = tid; i < 8192; i += 256) loc += g_bsum[i];
        sd[tid] = loc;
        __syncthreads();
        for (int off = 128; off > 0; off >>= 1) {
            if (tid < off) sd[tid] += sd[tid + off];
            __syncthreads();
        }
        if (tid == 0 && out_size >= NQ + 3) {
            float mse = (float)(sd[0] / (double)NQ);
            out[NQ + 0] = mse + 0.25f * mse;
            out[NQ + 1] = mse;
            out[NQ + 2] = mse;
        }
    } else {
        int i = (blockIdx.x - 1) * 256 + threadIdx.x;
        if (i < NPTS && out_size >= NQ + 3 + NPTS)
            out[NQ + 3 + i] = (float)g_enc[i];
    }
}

extern "C" void kernel_launch(void* const* d_in, const int* in_sizes, int n_in,
                              void* d_out, int out_size) {
    const float* x   = (const float*)d_in[0];
    const float* emb = (const float*)d_in[1];
    if (n_in >= 2 && in_sizes[0] == KK * DDIM && in_sizes[1] == NQ) {
        const float* tmp = x; x = emb; emb = tmp;
    }
    float* out = (float*)d_out;
    int do_store = (out_size >= NQ) ? 1 : 0;

    static int attr_set = 0;
    if (!attr_set) {
        cudaFuncSetAttribute(k_gemm, cudaFuncAttributeMaxDynamicSharedMemorySize, GEMM_DSMEM);
        attr_set = 1;
    }

    k_prep_e<<<KK, 256>>>(emb);
    k_prep_x<<<dim3(TT / 32, DDIM / 32, BN), dim3(32, 8)>>>(x);
    k_gemm<<<NPTS / 64, 256, GEMM_DSMEM>>>();
    k_passB<<<128, 256>>>(x, emb);
    k_quant<<<NQ / (256 * 4), 256>>>(x, emb, out, do_store);
    k_finish<<<1 + NPTS / 256, 256>>>(out, out_size);
}